// round 7
// baseline (speedup 1.0000x reference)
#include <cuda_runtime.h>
#include <cuda_fp16.h>
#include <math.h>
#include <cstdint>

#define NN 16384
#define DD 512
#define OO 512
#define BM 128
#define BN 64
#define BK 64                   // k-tile in elements (fp16)
#define NKT (DD / BK)           // 8 k-tiles
#define LH 72                   // smem fp16 per row (144B) -> conflict-free ldmatrix
#define TXH (BM * LH)           // 9216 halfs, X tile
#define TBH (BN * LH)           // 4608 halfs, P or A tile
#define STAGE_H (TXH + 2 * TBH) // 18432 halfs = 36864 B
#define SMEM_BYTES (2 * STAGE_H * 2)  // 73728 B, 2 stages -> 3 CTAs/SM
#define MINN 1e-15f

// Precomputed stats + fp16 operand copies (no allocations -> device globals).
__device__ float g_a0[NN];    // 1 + ||x||^2
__device__ float g_rr[NN];    // 2 / (1 - ||x||^2)
__device__ float g_B[OO];     // 1 - ||p||^2   (fp64-accurate)
__device__ float g_pa[OO];    // <p, a>
__device__ float g_q[OO];     // 1 / (B * ||a||)
__device__ float g_e2[OO];    // ln(2) * exp(scale)
__device__ __half g_Xh[NN * DD];
__device__ __half g_Ph[OO * DD];
__device__ __half g_Ah[OO * DD];

__device__ __forceinline__ float warp_sum(float v) {
#pragma unroll
    for (int s = 16; s > 0; s >>= 1) v += __shfl_xor_sync(0xffffffffu, v, s);
    return v;
}
__device__ __forceinline__ double warp_sum_d(double v) {
#pragma unroll
    for (int s = 16; s > 0; s >>= 1) v += __shfl_xor_sync(0xffffffffu, v, s);
    return v;
}
__device__ __forceinline__ uint2 cvt4(float4 v) {
    __half2 h0 = __floats2half2_rn(v.x, v.y);
    __half2 h1 = __floats2half2_rn(v.z, v.w);
    uint2 u;
    u.x = *reinterpret_cast<uint32_t*>(&h0);
    u.y = *reinterpret_cast<uint32_t*>(&h1);
    return u;
}

// ---------------- fused prep: X convert + x-stats | P/A convert + o-stats ----
__global__ void prep(const float* __restrict__ X, const float* __restrict__ P,
                     const float* __restrict__ A, const float* __restrict__ S) {
    int bid = blockIdx.x;
    int tid = threadIdx.x;
    int wid = tid >> 5, lane = tid & 31;
    if (bid < 2048) {
        int row = bid * 8 + wid;
        const float4* x4 = reinterpret_cast<const float4*>(X + (size_t)row * DD);
        uint2* xh = reinterpret_cast<uint2*>(g_Xh + (size_t)row * DD);
        float s = 0.f;
#pragma unroll
        for (int j = 0; j < 4; j++) {
            int idx = lane + 32 * j;
            float4 v = x4[idx];
            xh[idx] = cvt4(v);
            s += v.x * v.x + v.y * v.y + v.z * v.z + v.w * v.w;
        }
        s = warp_sum(s);
        if (lane == 0) {
            g_a0[row] = 1.f + s;
            g_rr[row] = 2.f / (1.f - s);
        }
    } else {
        int o = bid - 2048;
        __shared__ double sp2[4];
        __shared__ float spa[4], sa2[4];
        double p2 = 0.0;
        float pa = 0.f, a2 = 0.f;
        if (tid < 128) {
            const float4* p4 = reinterpret_cast<const float4*>(P + (size_t)o * DD);
            const float4* a4 = reinterpret_cast<const float4*>(A + (size_t)o * DD);
            uint2* ph = reinterpret_cast<uint2*>(g_Ph + (size_t)o * DD);
            uint2* ah = reinterpret_cast<uint2*>(g_Ah + (size_t)o * DD);
            float4 pv = p4[tid];
            float4 av = a4[tid];
            ph[tid] = cvt4(pv);
            ah[tid] = cvt4(av);
            p2 = (double)pv.x * pv.x + (double)pv.y * pv.y +
                 (double)pv.z * pv.z + (double)pv.w * pv.w;
            pa = pv.x * av.x + pv.y * av.y + pv.z * av.z + pv.w * av.w;
            a2 = av.x * av.x + av.y * av.y + av.z * av.z + av.w * av.w;
            p2 = warp_sum_d(p2);
            pa = warp_sum(pa);
            a2 = warp_sum(a2);
            if (lane == 0) { sp2[wid] = p2; spa[wid] = pa; sa2[wid] = a2; }
        }
        __syncthreads();
        if (tid == 0) {
            double tp2 = sp2[0] + sp2[1] + sp2[2] + sp2[3];
            float tpa = spa[0] + spa[1] + spa[2] + spa[3];
            float ta2 = sa2[0] + sa2[1] + sa2[2] + sa2[3];
            double B = 1.0 - tp2;    // catastrophic cancellation handled in fp64
            double an = sqrt((double)ta2);
            if (an < (double)MINN) an = (double)MINN;
            g_B[o] = (float)B;
            g_pa[o] = tpa;
            g_q[o] = (float)(1.0 / (B * an));
            g_e2[o] = 0.69314718055994530942f * expf(S[o]);
        }
    }
}

// ---------------- PTX helpers ----------------
#define MMA_F16(d, a, b0, b1)                                                  \
    asm volatile(                                                              \
        "mma.sync.aligned.m16n8k16.row.col.f32.f16.f16.f32 "                   \
        "{%0,%1,%2,%3}, {%4,%5,%6,%7}, {%8,%9}, {%0,%1,%2,%3};"                \
        : "+f"((d)[0]), "+f"((d)[1]), "+f"((d)[2]), "+f"((d)[3])               \
        : "r"((a)[0]), "r"((a)[1]), "r"((a)[2]), "r"((a)[3]), "r"(b0), "r"(b1))

#define LDMX4(r, addr)                                                         \
    asm volatile("ldmatrix.sync.aligned.m8n8.x4.shared.b16 {%0,%1,%2,%3}, [%4];" \
                 : "=r"((r)[0]), "=r"((r)[1]), "=r"((r)[2]), "=r"((r)[3])      \
                 : "r"(addr))

#define CPA16(saddr, gptr)                                                     \
    asm volatile("cp.async.cg.shared.global [%0], [%1], 16;"                   \
                 :: "r"(saddr), "l"(gptr))
#define CPA_COMMIT() asm volatile("cp.async.commit_group;" ::: "memory")
#define CPA_WAIT1() asm volatile("cp.async.wait_group 1;" ::: "memory")

// asinh(arg)*e^s via fast MUFU: asinh t = ln(t+sqrt(t^2+1)) = lg2(.)*ln2
__device__ __forceinline__ float epi(float xp, float xa, float a0, float rr,
                                     float B, float pa, float q, float e2) {
    float Aa = fmaf(-2.f, xp, a0);      // A = 1 + x^2 - 2*xp
    float tn = fmaf(B, xa, -Aa * pa);   // B*xa - A*pa
    float arg = tn * rr * q;            // 2*tn / (B*(1-x^2)*||a||)
    float tt = fabsf(arg);
    float s;
    asm("sqrt.approx.f32 %0, %1;" : "=f"(s) : "f"(fmaf(tt, tt, 1.f)));
    float u = tt + s;
    float r;
    asm("lg2.approx.f32 %0, %1;" : "=f"(r) : "f"(u));
    return copysignf(r * e2, arg);
}

// ---------------- main: fp16 mma.sync dual-GEMM + analytic Mobius epilogue ----
// 128x64 block tile, 256 threads, warp grid 2(M) x 4(N), warp tile 64x16.
// 2-stage cp.async pipeline, ldmatrix fragments, 3 CTAs/SM.
__global__ void __launch_bounds__(256, 3) mobius_main(float* __restrict__ out) {
    extern __shared__ __half smh[];
    int tid = threadIdx.x;
    int lane = tid & 31, wid = tid >> 5;
    int wm = wid & 1, wn = wid >> 1;
    int m0 = blockIdx.y * BM, n0 = blockIdx.x * BN;

    const __half* Xg = g_Xh + (size_t)m0 * DD;
    const __half* Pg = g_Ph + (size_t)n0 * DD;
    const __half* Ag = g_Ah + (size_t)n0 * DD;
    uint32_t sbase = (uint32_t)__cvta_generic_to_shared(smh);

#define LOAD_STAGE(stg, kt)                                                    \
    {                                                                          \
        uint32_t st = sbase + (uint32_t)(stg) * (STAGE_H * 2);                 \
        int k0 = (kt) * BK;                                                    \
        _Pragma("unroll") for (int j = 0; j < 4; j++) {  /* X: 1024 chunks */  \
            int f = tid + 256 * j;                                             \
            int row = f >> 3, ck = f & 7;                                      \
            CPA16(st + (uint32_t)(row * (LH * 2) + ck * 16),                   \
                  Xg + (size_t)row * DD + k0 + ck * 8);                        \
        }                                                                      \
        _Pragma("unroll") for (int j = 0; j < 2; j++) {  /* P: 512 chunks */   \
            int f = tid + 256 * j;                                             \
            int row = f >> 3, ck = f & 7;                                      \
            CPA16(st + (uint32_t)(TXH * 2 + row * (LH * 2) + ck * 16),         \
                  Pg + (size_t)row * DD + k0 + ck * 8);                        \
        }                                                                      \
        _Pragma("unroll") for (int j = 0; j < 2; j++) {  /* A: 512 chunks */   \
            int f = tid + 256 * j;                                             \
            int row = f >> 3, ck = f & 7;                                      \
            CPA16(st + (uint32_t)((TXH + TBH) * 2 + row * (LH * 2) + ck * 16), \
                  Ag + (size_t)row * DD + k0 + ck * 8);                        \
        }                                                                      \
    }

    float accP[4][2][4];
    float accA[4][2][4];
#pragma unroll
    for (int mt = 0; mt < 4; mt++)
#pragma unroll
        for (int nt = 0; nt < 2; nt++)
#pragma unroll
            for (int e = 0; e < 4; e++) { accP[mt][nt][e] = 0.f; accA[mt][nt][e] = 0.f; }

    LOAD_STAGE(0, 0); CPA_COMMIT();
    LOAD_STAGE(1, 1); CPA_COMMIT();

    // ldmatrix per-lane base addresses (bytes, within a stage)
    // A (x tile): lanes 0-7 -> m0-7 k0 | 8-15 -> m8-15 k0 | 16-23 -> m0-7 k8 | 24-31 -> m8-15 k8
    uint32_t a_base = (uint32_t)(((wm * 64 + (lane & 15)) * LH + ((lane >> 4) << 3)) * 2);
    // B (p/a tiles): lanes 0-7 -> n0-7 k0 | 8-15 -> n0-7 k8 | 16-23 -> n8-15 k0 | 24-31 -> n8-15 k8
    uint32_t b_row = (uint32_t)(wn * 16 + (((lane >> 4) & 1) << 3) + (lane & 7));
    uint32_t b_base = (uint32_t)((b_row * LH + (((lane >> 3) & 1) << 3)) * 2);

    for (int c = 0; c < NKT; ++c) {
        CPA_WAIT1();
        __syncthreads();

        uint32_t st = sbase + (uint32_t)(c & 1) * (STAGE_H * 2);
        uint32_t aA = st + a_base;
        uint32_t aP = st + TXH * 2 + b_base;
        uint32_t aT = aP + TBH * 2;
#pragma unroll
        for (int ks = 0; ks < 4; ks++) {    // 4 x k16 per k-tile of 64
            uint32_t af[4][4], bp[4], ba[4];
#pragma unroll
            for (int mt = 0; mt < 4; mt++)
                LDMX4(af[mt], aA + (uint32_t)(mt * 16 * LH * 2 + ks * 32));
            LDMX4(bp, aP + (uint32_t)(ks * 32));
            LDMX4(ba, aT + (uint32_t)(ks * 32));
#pragma unroll
            for (int nt = 0; nt < 2; nt++) {
#pragma unroll
                for (int mt = 0; mt < 4; mt++) {
                    MMA_F16(accP[mt][nt], af[mt], bp[2 * nt], bp[2 * nt + 1]);
                    MMA_F16(accA[mt][nt], af[mt], ba[2 * nt], ba[2 * nt + 1]);
                }
            }
        }
        __syncthreads();
        if (c + 2 < NKT) { LOAD_STAGE(c & 1, c + 2); }
        CPA_COMMIT();
    }

    // ---- epilogue ----
    int g = lane >> 2, t = lane & 3;
    float a0r[4][2], rrr[4][2];
#pragma unroll
    for (int mt = 0; mt < 4; mt++)
#pragma unroll
        for (int h = 0; h < 2; h++) {
            int r = m0 + wm * 64 + mt * 16 + g + h * 8;
            a0r[mt][h] = g_a0[r];
            rrr[mt][h] = g_rr[r];
        }
    float Bc[2][2], pac[2][2], qc[2][2], e2c[2][2];
#pragma unroll
    for (int nt = 0; nt < 2; nt++)
#pragma unroll
        for (int w = 0; w < 2; w++) {
            int cc = n0 + wn * 16 + nt * 8 + 2 * t + w;
            Bc[nt][w] = g_B[cc];
            pac[nt][w] = g_pa[cc];
            qc[nt][w] = g_q[cc];
            e2c[nt][w] = g_e2[cc];
        }
#pragma unroll
    for (int mt = 0; mt < 4; mt++) {
#pragma unroll
        for (int h = 0; h < 2; h++) {
            int r = m0 + wm * 64 + mt * 16 + g + h * 8;
            float* orow = out + (size_t)r * OO + n0 + wn * 16 + 2 * t;
#pragma unroll
            for (int nt = 0; nt < 2; nt++) {
                float o0 = epi(accP[mt][nt][h * 2 + 0], accA[mt][nt][h * 2 + 0],
                               a0r[mt][h], rrr[mt][h],
                               Bc[nt][0], pac[nt][0], qc[nt][0], e2c[nt][0]);
                float o1 = epi(accP[mt][nt][h * 2 + 1], accA[mt][nt][h * 2 + 1],
                               a0r[mt][h], rrr[mt][h],
                               Bc[nt][1], pac[nt][1], qc[nt][1], e2c[nt][1]);
                *reinterpret_cast<float2*>(orow + nt * 8) = make_float2(o0, o1);
            }
        }
    }
}

extern "C" void kernel_launch(void* const* d_in, const int* in_sizes, int n_in,
                              void* d_out, int out_size) {
    const float* x = (const float*)d_in[0];      // [N, D]
    const float* p = (const float*)d_in[1];      // [O, D]
    const float* a = (const float*)d_in[2];      // [O, D]
    const float* s = (const float*)d_in[3];      // [O]
    float* out = (float*)d_out;                  // [N, O]

    prep<<<2048 + OO, 256>>>(x, p, a, s);
    cudaFuncSetAttribute(mobius_main, cudaFuncAttributeMaxDynamicSharedMemorySize,
                         SMEM_BYTES);
    dim3 grid(OO / BN, NN / BM);
    mobius_main<<<grid, 256, SMEM_BYTES>>>(out);
}

// round 8
// speedup vs baseline: 1.4527x; 1.4527x over previous
#include <cuda_runtime.h>
#include <cuda_fp16.h>
#include <math.h>
#include <cstdint>

#define NN 16384
#define DD 512
#define OO 512
#define BM 128
#define BN 64
#define BK 64                   // k-tile in elements (fp16)
#define NKT (DD / BK)           // 8 k-tiles
#define LH 72                   // smem fp16 per row (144B) -> conflict-free ldmatrix
#define TXH (BM * LH)           // 9216 halfs, X tile
#define TBH (BN * LH)           // 4608 halfs, P or A tile
#define STAGE_H (TXH + 2 * TBH) // 18432 halfs = 36864 B
#define SMEM_BYTES (3 * STAGE_H * 2)  // 110592 B, 3 stages -> 2 CTAs/SM
#define MINN 1e-15f

// Precomputed stats + fp16 operand copies (no allocations -> device globals).
__device__ float g_a0[NN];    // 1 + ||x||^2
__device__ float g_rr[NN];    // 2 / (1 - ||x||^2)
__device__ float g_B[OO];     // 1 - ||p||^2   (fp64-accurate)
__device__ float g_pa[OO];    // <p, a>
__device__ float g_q[OO];     // 1 / (B * ||a||)
__device__ float g_e2[OO];    // ln(2) * exp(scale)
__device__ __half g_Xh[NN * DD];
__device__ __half g_Ph[OO * DD];
__device__ __half g_Ah[OO * DD];

__device__ __forceinline__ float warp_sum(float v) {
#pragma unroll
    for (int s = 16; s > 0; s >>= 1) v += __shfl_xor_sync(0xffffffffu, v, s);
    return v;
}
__device__ __forceinline__ double warp_sum_d(double v) {
#pragma unroll
    for (int s = 16; s > 0; s >>= 1) v += __shfl_xor_sync(0xffffffffu, v, s);
    return v;
}
__device__ __forceinline__ uint2 cvt4(float4 v) {
    __half2 h0 = __floats2half2_rn(v.x, v.y);
    __half2 h1 = __floats2half2_rn(v.z, v.w);
    uint2 u;
    u.x = *reinterpret_cast<uint32_t*>(&h0);
    u.y = *reinterpret_cast<uint32_t*>(&h1);
    return u;
}

// ---------------- fused prep: X convert + x-stats | P/A convert + o-stats ----
__global__ void prep(const float* __restrict__ X, const float* __restrict__ P,
                     const float* __restrict__ A, const float* __restrict__ S) {
    int bid = blockIdx.x;
    int tid = threadIdx.x;
    int wid = tid >> 5, lane = tid & 31;
    if (bid < 2048) {
        int row = bid * 8 + wid;
        const float4* x4 = reinterpret_cast<const float4*>(X + (size_t)row * DD);
        uint2* xh = reinterpret_cast<uint2*>(g_Xh + (size_t)row * DD);
        float s = 0.f;
#pragma unroll
        for (int j = 0; j < 4; j++) {
            int idx = lane + 32 * j;
            float4 v = x4[idx];
            xh[idx] = cvt4(v);
            s += v.x * v.x + v.y * v.y + v.z * v.z + v.w * v.w;
        }
        s = warp_sum(s);
        if (lane == 0) {
            g_a0[row] = 1.f + s;
            g_rr[row] = 2.f / (1.f - s);
        }
    } else {
        int o = bid - 2048;
        __shared__ double sp2[4];
        __shared__ float spa[4], sa2[4];
        double p2 = 0.0;
        float pa = 0.f, a2 = 0.f;
        if (tid < 128) {
            const float4* p4 = reinterpret_cast<const float4*>(P + (size_t)o * DD);
            const float4* a4 = reinterpret_cast<const float4*>(A + (size_t)o * DD);
            uint2* ph = reinterpret_cast<uint2*>(g_Ph + (size_t)o * DD);
            uint2* ah = reinterpret_cast<uint2*>(g_Ah + (size_t)o * DD);
            float4 pv = p4[tid];
            float4 av = a4[tid];
            ph[tid] = cvt4(pv);
            ah[tid] = cvt4(av);
            p2 = (double)pv.x * pv.x + (double)pv.y * pv.y +
                 (double)pv.z * pv.z + (double)pv.w * pv.w;
            pa = pv.x * av.x + pv.y * av.y + pv.z * av.z + pv.w * av.w;
            a2 = av.x * av.x + av.y * av.y + av.z * av.z + av.w * av.w;
            p2 = warp_sum_d(p2);
            pa = warp_sum(pa);
            a2 = warp_sum(a2);
            if (lane == 0) { sp2[wid] = p2; spa[wid] = pa; sa2[wid] = a2; }
        }
        __syncthreads();
        if (tid == 0) {
            double tp2 = sp2[0] + sp2[1] + sp2[2] + sp2[3];
            float tpa = spa[0] + spa[1] + spa[2] + spa[3];
            float ta2 = sa2[0] + sa2[1] + sa2[2] + sa2[3];
            double B = 1.0 - tp2;    // catastrophic cancellation handled in fp64
            double an = sqrt((double)ta2);
            if (an < (double)MINN) an = (double)MINN;
            g_B[o] = (float)B;
            g_pa[o] = tpa;
            g_q[o] = (float)(1.0 / (B * an));
            g_e2[o] = 0.69314718055994530942f * expf(S[o]);
        }
    }
}

// ---------------- PTX helpers ----------------
#define MMA_F16(d, a, b0, b1)                                                  \
    asm volatile(                                                              \
        "mma.sync.aligned.m16n8k16.row.col.f32.f16.f16.f32 "                   \
        "{%0,%1,%2,%3}, {%4,%5,%6,%7}, {%8,%9}, {%0,%1,%2,%3};"                \
        : "+f"((d)[0]), "+f"((d)[1]), "+f"((d)[2]), "+f"((d)[3])               \
        : "r"((a)[0]), "r"((a)[1]), "r"((a)[2]), "r"((a)[3]), "r"(b0), "r"(b1))

#define LDMX4(r, addr)                                                         \
    asm volatile("ldmatrix.sync.aligned.m8n8.x4.shared.b16 {%0,%1,%2,%3}, [%4];" \
                 : "=r"((r)[0]), "=r"((r)[1]), "=r"((r)[2]), "=r"((r)[3])      \
                 : "r"(addr))

#define CPA16(saddr, gptr)                                                     \
    asm volatile("cp.async.cg.shared.global [%0], [%1], 16;"                   \
                 :: "r"(saddr), "l"(gptr))
#define CPA_COMMIT() asm volatile("cp.async.commit_group;" ::: "memory")
#define CPA_WAIT1() asm volatile("cp.async.wait_group 1;" ::: "memory")

// asinh(arg)*e^s via fast MUFU: asinh t = ln(t+sqrt(t^2+1)) = lg2(.)*ln2
__device__ __forceinline__ float epi(float xp, float xa, float a0, float rr,
                                     float B, float pa, float q, float e2) {
    float Aa = fmaf(-2.f, xp, a0);      // A = 1 + x^2 - 2*xp
    float tn = fmaf(B, xa, -Aa * pa);   // B*xa - A*pa
    float arg = tn * rr * q;            // 2*tn / (B*(1-x^2)*||a||)
    float tt = fabsf(arg);
    float s;
    asm("sqrt.approx.f32 %0, %1;" : "=f"(s) : "f"(fmaf(tt, tt, 1.f)));
    float u = tt + s;
    float r;
    asm("lg2.approx.f32 %0, %1;" : "=f"(r) : "f"(u));
    return copysignf(r * e2, arg);
}

// ---------------- main: fp16 mma.sync dual-GEMM + analytic Mobius epilogue ----
// 128x64 block tile, 256 threads, warp grid 2(M) x 4(N), warp tile 64x16.
// Round-6 pipeline (3 stages, load-before-compute, one barrier) + ldmatrix frags.
__global__ void __launch_bounds__(256, 2) mobius_main(float* __restrict__ out) {
    extern __shared__ __half smh[];
    int tid = threadIdx.x;
    int lane = tid & 31, wid = tid >> 5;
    int wm = wid & 1, wn = wid >> 1;
    int m0 = blockIdx.y * BM, n0 = blockIdx.x * BN;

    const __half* Xg = g_Xh + (size_t)m0 * DD;
    const __half* Pg = g_Ph + (size_t)n0 * DD;
    const __half* Ag = g_Ah + (size_t)n0 * DD;
    uint32_t sbase = (uint32_t)__cvta_generic_to_shared(smh);

#define LOAD_STAGE(stg, kt)                                                    \
    {                                                                          \
        uint32_t st = sbase + (uint32_t)(stg) * (STAGE_H * 2);                 \
        int k0 = (kt) * BK;                                                    \
        _Pragma("unroll") for (int j = 0; j < 4; j++) {  /* X: 1024 chunks */  \
            int f = tid + 256 * j;                                             \
            int row = f >> 3, ck = f & 7;                                      \
            CPA16(st + (uint32_t)(row * (LH * 2) + ck * 16),                   \
                  Xg + (size_t)row * DD + k0 + ck * 8);                        \
        }                                                                      \
        _Pragma("unroll") for (int j = 0; j < 2; j++) {  /* P: 512 chunks */   \
            int f = tid + 256 * j;                                             \
            int row = f >> 3, ck = f & 7;                                      \
            CPA16(st + (uint32_t)(TXH * 2 + row * (LH * 2) + ck * 16),         \
                  Pg + (size_t)row * DD + k0 + ck * 8);                        \
        }                                                                      \
        _Pragma("unroll") for (int j = 0; j < 2; j++) {  /* A: 512 chunks */   \
            int f = tid + 256 * j;                                             \
            int row = f >> 3, ck = f & 7;                                      \
            CPA16(st + (uint32_t)((TXH + TBH) * 2 + row * (LH * 2) + ck * 16), \
                  Ag + (size_t)row * DD + k0 + ck * 8);                        \
        }                                                                      \
    }

    float accP[4][2][4];
    float accA[4][2][4];
#pragma unroll
    for (int mt = 0; mt < 4; mt++)
#pragma unroll
        for (int nt = 0; nt < 2; nt++)
#pragma unroll
            for (int e = 0; e < 4; e++) { accP[mt][nt][e] = 0.f; accA[mt][nt][e] = 0.f; }

    LOAD_STAGE(0, 0); CPA_COMMIT();
    LOAD_STAGE(1, 1); CPA_COMMIT();

    // ldmatrix per-lane base addresses (bytes, within a stage)
    // A (x tile): lanes 0-7 -> m0-7 k0 | 8-15 -> m8-15 k0 | 16-23 -> m0-7 k8 | 24-31 -> m8-15 k8
    uint32_t a_base = (uint32_t)(((wm * 64 + (lane & 15)) * LH + ((lane >> 4) << 3)) * 2);
    // B (p/a tiles): lanes 0-7 -> n0-7 k0 | 8-15 -> n0-7 k8 | 16-23 -> n8-15 k0 | 24-31 -> n8-15 k8
    uint32_t b_row = (uint32_t)(wn * 16 + (((lane >> 4) & 1) << 3) + (lane & 7));
    uint32_t b_base = (uint32_t)((b_row * LH + (((lane >> 3) & 1) << 3)) * 2);

    for (int c = 0; c < NKT; ++c) {
        CPA_WAIT1();
        __syncthreads();
        if (c + 2 < NKT) { LOAD_STAGE((c + 2) % 3, c + 2); }
        CPA_COMMIT();

        uint32_t st = sbase + (uint32_t)(c % 3) * (STAGE_H * 2);
        uint32_t aA = st + a_base;
        uint32_t aP = st + TXH * 2 + b_base;
        uint32_t aT = aP + TBH * 2;
#pragma unroll
        for (int ks = 0; ks < 4; ks++) {    // 4 x k16 per k-tile of 64
            uint32_t af[4][4], bp[4], ba[4];
#pragma unroll
            for (int mt = 0; mt < 4; mt++)
                LDMX4(af[mt], aA + (uint32_t)(mt * 16 * LH * 2 + ks * 32));
            LDMX4(bp, aP + (uint32_t)(ks * 32));
            LDMX4(ba, aT + (uint32_t)(ks * 32));
#pragma unroll
            for (int nt = 0; nt < 2; nt++) {
#pragma unroll
                for (int mt = 0; mt < 4; mt++) {
                    MMA_F16(accP[mt][nt], af[mt], bp[2 * nt], bp[2 * nt + 1]);
                    MMA_F16(accA[mt][nt], af[mt], ba[2 * nt], ba[2 * nt + 1]);
                }
            }
        }
    }

    // ---- epilogue ----
    int g = lane >> 2, t = lane & 3;
    float a0r[4][2], rrr[4][2];
#pragma unroll
    for (int mt = 0; mt < 4; mt++)
#pragma unroll
        for (int h = 0; h < 2; h++) {
            int r = m0 + wm * 64 + mt * 16 + g + h * 8;
            a0r[mt][h] = g_a0[r];
            rrr[mt][h] = g_rr[r];
        }
    float Bc[2][2], pac[2][2], qc[2][2], e2c[2][2];
#pragma unroll
    for (int nt = 0; nt < 2; nt++)
#pragma unroll
        for (int w = 0; w < 2; w++) {
            int cc = n0 + wn * 16 + nt * 8 + 2 * t + w;
            Bc[nt][w] = g_B[cc];
            pac[nt][w] = g_pa[cc];
            qc[nt][w] = g_q[cc];
            e2c[nt][w] = g_e2[cc];
        }
#pragma unroll
    for (int mt = 0; mt < 4; mt++) {
#pragma unroll
        for (int h = 0; h < 2; h++) {
            int r = m0 + wm * 64 + mt * 16 + g + h * 8;
            float* orow = out + (size_t)r * OO + n0 + wn * 16 + 2 * t;
#pragma unroll
            for (int nt = 0; nt < 2; nt++) {
                float o0 = epi(accP[mt][nt][h * 2 + 0], accA[mt][nt][h * 2 + 0],
                               a0r[mt][h], rrr[mt][h],
                               Bc[nt][0], pac[nt][0], qc[nt][0], e2c[nt][0]);
                float o1 = epi(accP[mt][nt][h * 2 + 1], accA[mt][nt][h * 2 + 1],
                               a0r[mt][h], rrr[mt][h],
                               Bc[nt][1], pac[nt][1], qc[nt][1], e2c[nt][1]);
                *reinterpret_cast<float2*>(orow + nt * 8) = make_float2(o0, o1);
            }
        }
    }
}

extern "C" void kernel_launch(void* const* d_in, const int* in_sizes, int n_in,
                              void* d_out, int out_size) {
    const float* x = (const float*)d_in[0];      // [N, D]
    const float* p = (const float*)d_in[1];      // [O, D]
    const float* a = (const float*)d_in[2];      // [O, D]
    const float* s = (const float*)d_in[3];      // [O]
    float* out = (float*)d_out;                  // [N, O]

    prep<<<2048 + OO, 256>>>(x, p, a, s);
    cudaFuncSetAttribute(mobius_main, cudaFuncAttributeMaxDynamicSharedMemorySize,
                         SMEM_BYTES);
    dim3 grid(OO / BN, NN / BM);
    mobius_main<<<grid, 256, SMEM_BYTES>>>(out);
}

// round 9
// speedup vs baseline: 1.4574x; 1.0032x over previous
#include <cuda_runtime.h>
#include <cuda_fp16.h>
#include <math.h>
#include <cstdint>

#define NN 16384
#define DD 512
#define OO 512
#define BM 128
#define BN 64
#define BK 64                   // k-tile in elements (fp16)
#define NKT (DD / BK)           // 8 k-tiles
#define LH 72                   // smem fp16 per row (144B) -> conflict-free ldmatrix
#define TXH (BM * LH)           // 9216 halfs, X tile
#define TBH (BN * LH)           // 4608 halfs, P or A tile
#define STAGE_H (TXH + 2 * TBH) // 18432 halfs = 36864 B
#define SMEM_BYTES (3 * STAGE_H * 2)  // 110592 B, 3 stages -> 2 CTAs/SM
#define MINN 1e-15f

// Precomputed stats + fp16 operand copies (no allocations -> device globals).
__device__ float g_a0[NN];    // 1 + ||x||^2
__device__ float g_rr[NN];    // 2 / (1 - ||x||^2)
__device__ float g_B[OO];     // 1 - ||p||^2   (fp64-accurate)
__device__ float g_pa[OO];    // <p, a>
__device__ float g_q[OO];     // 1 / (B * ||a||)
__device__ float g_e2[OO];    // ln(2) * exp(scale)
__device__ __half g_Xh[NN * DD];
__device__ __half g_Ph[OO * DD];
__device__ __half g_Ah[OO * DD];

__device__ __forceinline__ float warp_sum(float v) {
#pragma unroll
    for (int s = 16; s > 0; s >>= 1) v += __shfl_xor_sync(0xffffffffu, v, s);
    return v;
}
__device__ __forceinline__ double warp_sum_d(double v) {
#pragma unroll
    for (int s = 16; s > 0; s >>= 1) v += __shfl_xor_sync(0xffffffffu, v, s);
    return v;
}
__device__ __forceinline__ uint2 cvt4(float4 v) {
    __half2 h0 = __floats2half2_rn(v.x, v.y);
    __half2 h1 = __floats2half2_rn(v.z, v.w);
    uint2 u;
    u.x = *reinterpret_cast<uint32_t*>(&h0);
    u.y = *reinterpret_cast<uint32_t*>(&h1);
    return u;
}

// ---------------- fused prep: X convert + x-stats | P/A convert + o-stats ----
__global__ void prep(const float* __restrict__ X, const float* __restrict__ P,
                     const float* __restrict__ A, const float* __restrict__ S) {
    int bid = blockIdx.x;
    int tid = threadIdx.x;
    int wid = tid >> 5, lane = tid & 31;
    if (bid < 2048) {
        int row = bid * 8 + wid;
        const float4* x4 = reinterpret_cast<const float4*>(X + (size_t)row * DD);
        uint2* xh = reinterpret_cast<uint2*>(g_Xh + (size_t)row * DD);
        float s = 0.f;
#pragma unroll
        for (int j = 0; j < 4; j++) {
            int idx = lane + 32 * j;
            float4 v = x4[idx];
            xh[idx] = cvt4(v);
            s += v.x * v.x + v.y * v.y + v.z * v.z + v.w * v.w;
        }
        s = warp_sum(s);
        if (lane == 0) {
            g_a0[row] = 1.f + s;
            g_rr[row] = 2.f / (1.f - s);
        }
    } else {
        int o = bid - 2048;
        __shared__ double sp2[4];
        __shared__ float spa[4], sa2[4];
        double p2 = 0.0;
        float pa = 0.f, a2 = 0.f;
        if (tid < 128) {
            const float4* p4 = reinterpret_cast<const float4*>(P + (size_t)o * DD);
            const float4* a4 = reinterpret_cast<const float4*>(A + (size_t)o * DD);
            uint2* ph = reinterpret_cast<uint2*>(g_Ph + (size_t)o * DD);
            uint2* ah = reinterpret_cast<uint2*>(g_Ah + (size_t)o * DD);
            float4 pv = p4[tid];
            float4 av = a4[tid];
            ph[tid] = cvt4(pv);
            ah[tid] = cvt4(av);
            p2 = (double)pv.x * pv.x + (double)pv.y * pv.y +
                 (double)pv.z * pv.z + (double)pv.w * pv.w;
            pa = pv.x * av.x + pv.y * av.y + pv.z * av.z + pv.w * av.w;
            a2 = av.x * av.x + av.y * av.y + av.z * av.z + av.w * av.w;
            p2 = warp_sum_d(p2);
            pa = warp_sum(pa);
            a2 = warp_sum(a2);
            if (lane == 0) { sp2[wid] = p2; spa[wid] = pa; sa2[wid] = a2; }
        }
        __syncthreads();
        if (tid == 0) {
            double tp2 = sp2[0] + sp2[1] + sp2[2] + sp2[3];
            float tpa = spa[0] + spa[1] + spa[2] + spa[3];
            float ta2 = sa2[0] + sa2[1] + sa2[2] + sa2[3];
            double B = 1.0 - tp2;    // catastrophic cancellation handled in fp64
            double an = sqrt((double)ta2);
            if (an < (double)MINN) an = (double)MINN;
            g_B[o] = (float)B;
            g_pa[o] = tpa;
            g_q[o] = (float)(1.0 / (B * an));
            g_e2[o] = 0.69314718055994530942f * expf(S[o]);
        }
    }
}

// ---------------- PTX helpers ----------------
#define MMA_F16(d, a, b0, b1)                                                  \
    asm volatile(                                                              \
        "mma.sync.aligned.m16n8k16.row.col.f32.f16.f16.f32 "                   \
        "{%0,%1,%2,%3}, {%4,%5,%6,%7}, {%8,%9}, {%0,%1,%2,%3};"                \
        : "+f"((d)[0]), "+f"((d)[1]), "+f"((d)[2]), "+f"((d)[3])               \
        : "r"((a)[0]), "r"((a)[1]), "r"((a)[2]), "r"((a)[3]), "r"(b0), "r"(b1))

#define LDMX4(r, addr)                                                         \
    asm volatile("ldmatrix.sync.aligned.m8n8.x4.shared.b16 {%0,%1,%2,%3}, [%4];" \
                 : "=r"((r)[0]), "=r"((r)[1]), "=r"((r)[2]), "=r"((r)[3])      \
                 : "r"(addr))

#define CPA16(saddr, gptr)                                                     \
    asm volatile("cp.async.cg.shared.global [%0], [%1], 16;"                   \
                 :: "r"(saddr), "l"(gptr))
#define CPA_COMMIT() asm volatile("cp.async.commit_group;" ::: "memory")
#define CPA_WAIT1() asm volatile("cp.async.wait_group 1;" ::: "memory")

// asinh(arg)*e^s: asinh t = ln(t+sqrt(t^2+1)) = lg2(.)*ln2.
// Fast path (warp-uniform): when all lanes have |t| >= 64,
// asinh(t) = ln(2t) + O(1/(4t^2))  (rel err <= 1.3e-5) -> skip the sqrt MUFU.
__device__ __forceinline__ float epi(float xp, float xa, float a0, float rr,
                                     float B, float pa, float q, float e2) {
    float Aa = fmaf(-2.f, xp, a0);      // A = 1 + x^2 - 2*xp
    float tn = fmaf(B, xa, -Aa * pa);   // B*xa - A*pa
    float arg = tn * rr * q;            // 2*tn / (B*(1-x^2)*||a||)
    float tt = fabsf(arg);
    float u;
    if (__any_sync(0xffffffffu, tt < 64.f)) {
        float s;
        asm("sqrt.approx.f32 %0, %1;" : "=f"(s) : "f"(fmaf(tt, tt, 1.f)));
        u = tt + s;
    } else {
        u = tt + tt;
    }
    float r;
    asm("lg2.approx.f32 %0, %1;" : "=f"(r) : "f"(u));
    return copysignf(r * e2, arg);
}

// ---------------- main: fp16 mma.sync dual-GEMM + analytic Mobius epilogue ----
// 128x64 block tile, 256 threads, warp grid 2(M) x 4(N), warp tile 64x16.
// 3-stage cp.async pipeline + register-level fragment double-buffering.
__global__ void __launch_bounds__(256, 2) mobius_main(float* __restrict__ out) {
    extern __shared__ __half smh[];
    int tid = threadIdx.x;
    int lane = tid & 31, wid = tid >> 5;
    int wm = wid & 1, wn = wid >> 1;
    int m0 = blockIdx.y * BM, n0 = blockIdx.x * BN;

    const __half* Xg = g_Xh + (size_t)m0 * DD;
    const __half* Pg = g_Ph + (size_t)n0 * DD;
    const __half* Ag = g_Ah + (size_t)n0 * DD;
    uint32_t sbase = (uint32_t)__cvta_generic_to_shared(smh);

#define LOAD_STAGE(stg, kt)                                                    \
    {                                                                          \
        uint32_t st = sbase + (uint32_t)(stg) * (STAGE_H * 2);                 \
        int k0 = (kt) * BK;                                                    \
        _Pragma("unroll") for (int j = 0; j < 4; j++) {  /* X: 1024 chunks */  \
            int f = tid + 256 * j;                                             \
            int row = f >> 3, ck = f & 7;                                      \
            CPA16(st + (uint32_t)(row * (LH * 2) + ck * 16),                   \
                  Xg + (size_t)row * DD + k0 + ck * 8);                        \
        }                                                                      \
        _Pragma("unroll") for (int j = 0; j < 2; j++) {  /* P: 512 chunks */   \
            int f = tid + 256 * j;                                             \
            int row = f >> 3, ck = f & 7;                                      \
            CPA16(st + (uint32_t)(TXH * 2 + row * (LH * 2) + ck * 16),         \
                  Pg + (size_t)row * DD + k0 + ck * 8);                        \
        }                                                                      \
        _Pragma("unroll") for (int j = 0; j < 2; j++) {  /* A: 512 chunks */   \
            int f = tid + 256 * j;                                             \
            int row = f >> 3, ck = f & 7;                                      \
            CPA16(st + (uint32_t)((TXH + TBH) * 2 + row * (LH * 2) + ck * 16), \
                  Ag + (size_t)row * DD + k0 + ck * 8);                        \
        }                                                                      \
    }

    float accP[4][2][4];
    float accA[4][2][4];
#pragma unroll
    for (int mt = 0; mt < 4; mt++)
#pragma unroll
        for (int nt = 0; nt < 2; nt++)
#pragma unroll
            for (int e = 0; e < 4; e++) { accP[mt][nt][e] = 0.f; accA[mt][nt][e] = 0.f; }

    LOAD_STAGE(0, 0); CPA_COMMIT();
    LOAD_STAGE(1, 1); CPA_COMMIT();

    // ldmatrix per-lane base addresses (bytes, within a stage)
    // A (x tile): lanes 0-7 -> m0-7 k0 | 8-15 -> m8-15 k0 | 16-23 -> m0-7 k8 | 24-31 -> m8-15 k8
    uint32_t a_base = (uint32_t)(((wm * 64 + (lane & 15)) * LH + ((lane >> 4) << 3)) * 2);
    // B (p/a tiles): lanes 0-7 -> n0-7 k0 | 8-15 -> n0-7 k8 | 16-23 -> n8-15 k0 | 24-31 -> n8-15 k8
    uint32_t b_row = (uint32_t)(wn * 16 + (((lane >> 4) & 1) << 3) + (lane & 7));
    uint32_t b_base = (uint32_t)((b_row * LH + (((lane >> 3) & 1) << 3)) * 2);

    for (int c = 0; c < NKT; ++c) {
        CPA_WAIT1();
        __syncthreads();
        if (c + 2 < NKT) { LOAD_STAGE((c + 2) % 3, c + 2); }
        CPA_COMMIT();

        uint32_t st = sbase + (uint32_t)(c % 3) * (STAGE_H * 2);
        uint32_t aA = st + a_base;
        uint32_t aP = st + TXH * 2 + b_base;
        uint32_t aT = aP + TBH * 2;

        // register double-buffered fragments across ks
        uint32_t af[2][4][4], bp[2][4], ba[2][4];
#pragma unroll
        for (int mt = 0; mt < 4; mt++)
            LDMX4(af[0][mt], aA + (uint32_t)(mt * 16 * LH * 2));
        LDMX4(bp[0], aP);
        LDMX4(ba[0], aT);

#pragma unroll
        for (int ks = 0; ks < 4; ks++) {    // 4 x k16 per k-tile of 64
            int cur = ks & 1, nxt = cur ^ 1;
            if (ks < 3) {
#pragma unroll
                for (int mt = 0; mt < 4; mt++)
                    LDMX4(af[nxt][mt],
                          aA + (uint32_t)(mt * 16 * LH * 2 + (ks + 1) * 32));
                LDMX4(bp[nxt], aP + (uint32_t)((ks + 1) * 32));
                LDMX4(ba[nxt], aT + (uint32_t)((ks + 1) * 32));
            }
#pragma unroll
            for (int nt = 0; nt < 2; nt++) {
#pragma unroll
                for (int mt = 0; mt < 4; mt++) {
                    MMA_F16(accP[mt][nt], af[cur][mt], bp[cur][2 * nt], bp[cur][2 * nt + 1]);
                    MMA_F16(accA[mt][nt], af[cur][mt], ba[cur][2 * nt], ba[cur][2 * nt + 1]);
                }
            }
        }
    }

    // ---- epilogue ----
    int g = lane >> 2, t = lane & 3;
    float a0r[4][2], rrr[4][2];
#pragma unroll
    for (int mt = 0; mt < 4; mt++)
#pragma unroll
        for (int h = 0; h < 2; h++) {
            int r = m0 + wm * 64 + mt * 16 + g + h * 8;
            a0r[mt][h] = g_a0[r];
            rrr[mt][h] = g_rr[r];
        }
    float Bc[2][2], pac[2][2], qc[2][2], e2c[2][2];
#pragma unroll
    for (int nt = 0; nt < 2; nt++)
#pragma unroll
        for (int w = 0; w < 2; w++) {
            int cc = n0 + wn * 16 + nt * 8 + 2 * t + w;
            Bc[nt][w] = g_B[cc];
            pac[nt][w] = g_pa[cc];
            qc[nt][w] = g_q[cc];
            e2c[nt][w] = g_e2[cc];
        }
#pragma unroll
    for (int mt = 0; mt < 4; mt++) {
#pragma unroll
        for (int h = 0; h < 2; h++) {
            int r = m0 + wm * 64 + mt * 16 + g + h * 8;
            float* orow = out + (size_t)r * OO + n0 + wn * 16 + 2 * t;
#pragma unroll
            for (int nt = 0; nt < 2; nt++) {
                float o0 = epi(accP[mt][nt][h * 2 + 0], accA[mt][nt][h * 2 + 0],
                               a0r[mt][h], rrr[mt][h],
                               Bc[nt][0], pac[nt][0], qc[nt][0], e2c[nt][0]);
                float o1 = epi(accP[mt][nt][h * 2 + 1], accA[mt][nt][h * 2 + 1],
                               a0r[mt][h], rrr[mt][h],
                               Bc[nt][1], pac[nt][1], qc[nt][1], e2c[nt][1]);
                *reinterpret_cast<float2*>(orow + nt * 8) = make_float2(o0, o1);
            }
        }
    }
}

extern "C" void kernel_launch(void* const* d_in, const int* in_sizes, int n_in,
                              void* d_out, int out_size) {
    const float* x = (const float*)d_in[0];      // [N, D]
    const float* p = (const float*)d_in[1];      // [O, D]
    const float* a = (const float*)d_in[2];      // [O, D]
    const float* s = (const float*)d_in[3];      // [O]
    float* out = (float*)d_out;                  // [N, O]

    prep<<<2048 + OO, 256>>>(x, p, a, s);
    cudaFuncSetAttribute(mobius_main, cudaFuncAttributeMaxDynamicSharedMemorySize,
                         SMEM_BYTES);
    dim3 grid(OO / BN, NN / BM);
    mobius_main<<<grid, 256, SMEM_BYTES>>>(out);
}